// round 7
// baseline (speedup 1.0000x reference)
#include <cuda_runtime.h>
#include <cuda_bf16.h>
#include <math.h>
#include <float.h>
#include <stdint.h>

#define T_STEPS 32
#define B_SZ    512
#define S_SZ    64
#define F_IN    128
#define H1      256
#define H2      256
#define H3      128
#define M_ROWS  (T_STEPS * B_SZ)   // 16384

// ---------------------------------------------------------------------------
// Scratch (__device__ globals; no allocation allowed)
// Row layout for activations: r = b*32 + t  (b-major)
// ---------------------------------------------------------------------------
__device__ __nv_bfloat16 g_spk0[M_ROWS * F_IN];
__device__ __nv_bfloat16 g_spk1[M_ROWS * H1];
__device__ __nv_bfloat16 g_spk2[M_ROWS * H2];
__device__ __nv_bfloat16 g_wsplit[9][H1 * H1];   // [layer*3+split][N*K]

// ---------------------------------------------------------------------------
// PTX helpers
// ---------------------------------------------------------------------------
__device__ __forceinline__ uint32_t smem_u32(const void* p) {
    uint32_t a;
    asm("{ .reg .u64 t; cvta.to.shared.u64 t, %1; cvt.u32.u64 %0, t; }" : "=r"(a) : "l"(p));
    return a;
}
#define CP_ASYNC16(dst, src) \
    asm volatile("cp.async.cg.shared.global [%0], [%1], 16;" :: "r"(dst), "l"(src))
#define CP_COMMIT() asm volatile("cp.async.commit_group;")
#define CP_WAIT(N)  asm volatile("cp.async.wait_group %0;" :: "n"(N))

#define LDSM_X4(r0, r1, r2, r3, addr)                                   \
    asm volatile("ldmatrix.sync.aligned.m8n8.x4.shared.b16 "            \
                 "{%0,%1,%2,%3}, [%4];"                                 \
                 : "=r"(r0), "=r"(r1), "=r"(r2), "=r"(r3) : "r"(addr))
#define LDSM_X2(r0, r1, addr)                                           \
    asm volatile("ldmatrix.sync.aligned.m8n8.x2.shared.b16 "            \
                 "{%0,%1}, [%2];" : "=r"(r0), "=r"(r1) : "r"(addr))

#define MMA_BF16(c, a, b0, b1)                                          \
    asm volatile("mma.sync.aligned.m16n8k16.row.col.f32.bf16.bf16.f32 " \
                 "{%0,%1,%2,%3}, {%4,%5,%6,%7}, {%8,%9}, {%0,%1,%2,%3};"\
                 : "+f"((c)[0]), "+f"((c)[1]), "+f"((c)[2]), "+f"((c)[3])\
                 : "r"((a)[0]), "r"((a)[1]), "r"((a)[2]), "r"((a)[3]),  \
                   "r"(b0), "r"(b1))

// ---------------------------------------------------------------------------
// Fused HMMA GEMM + LIF scan. 512 threads, 16 warps (4x4), warp tile 32x32
// (BM=128) or 16x32 (BM=64). BK=32, double-buffered cp.async.
// ---------------------------------------------------------------------------
#define BK        32
#define SROW_B    80
#define W_TILE_B  (128 * SROW_B)
#define SM_BIAS   0
#define SM_STAGE  512
#define STP       130                        // epilogue stage pitch (floats)
#define SM_TOTAL  (SM_STAGE + 2 * (128 * SROW_B + 3 * W_TILE_B))   // 82432

template<int K, int BM, bool FINAL>
__global__ __launch_bounds__(512)
void hmma_gemm_lif_kernel(const __nv_bfloat16* __restrict__ A,
                          const __nv_bfloat16* __restrict__ Whi,
                          const __nv_bfloat16* __restrict__ Wmid,
                          const __nv_bfloat16* __restrict__ Wlo,
                          const float* __restrict__ bias,
                          __nv_bfloat16* __restrict__ spk_out,
                          float* __restrict__ final_out,
                          int N) {
    constexpr int CHUNKS   = K / BK;
    constexpr int MI       = BM / 64;                 // m16 tiles per warp
    constexpr int A_TILE_B = BM * SROW_B;
    constexpr int STAGE_B  = A_TILE_B + 3 * W_TILE_B;

    extern __shared__ char smem[];
    const uint32_t sb = smem_u32(smem);
    const int tid  = threadIdx.x;
    const int wid  = tid >> 5;
    const int lane = tid & 31;
    const int warp_m = wid & 3;        // 0..3
    const int warp_n = wid >> 2;       // 0..3
    const int m0 = blockIdx.y * BM;
    const int n0 = blockIdx.x * 128;

    if (tid < 128) ((float*)(smem + SM_BIAS))[tid] = bias[n0 + tid];

    const __nv_bfloat16* Wp[3] = {Whi, Wmid, Wlo};

    auto prefetch = [&](int c, int buf) {
        uint32_t st = sb + SM_STAGE + buf * STAGE_B;
        // A tile: BM rows x 32 cols bf16 = BM*4 16B units
#pragma unroll
        for (int u = tid; u < BM * 4; u += 512) {
            int row = u >> 2, col16 = u & 3;
            const char* g = (const char*)(A + (size_t)(m0 + row) * K + c * BK + col16 * 8);
            CP_ASYNC16(st + row * SROW_B + col16 * 16, g);
        }
#pragma unroll
        for (int s = 0; s < 3; ++s) {
            uint32_t wst = st + A_TILE_B + s * W_TILE_B;
            int u = tid;                               // 512 units exactly
            int row = u >> 2, col16 = u & 3;
            const char* g = (const char*)(Wp[s] + (size_t)(n0 + row) * K + c * BK + col16 * 8);
            CP_ASYNC16(wst + row * SROW_B + col16 * 16, g);
        }
        CP_COMMIT();
    };

    float acc[MI][4][4];
#pragma unroll
    for (int mi = 0; mi < MI; ++mi)
#pragma unroll
        for (int ni = 0; ni < 4; ++ni)
#pragma unroll
            for (int j = 0; j < 4; ++j) acc[mi][ni][j] = 0.f;

    const int a_row = warp_m * (BM / 4) + (lane & 7) + ((lane >> 3) & 1) * 8;
    const int a_col = (lane >> 4) * 8;
    const int lb16  = lane & 15;
    const int b_row = warp_n * 32 + (lb16 & 7);
    const int b_col = ((lb16 >> 3) & 1) * 8;

    prefetch(0, 0);

    for (int c = 0; c < CHUNKS; ++c) {
        int buf = c & 1;
        if (c + 1 < CHUNKS) { prefetch(c + 1, buf ^ 1); CP_WAIT(1); }
        else                { CP_WAIT(0); }
        __syncthreads();

        uint32_t a_base = sb + SM_STAGE + buf * STAGE_B;
        uint32_t w_base = a_base + A_TILE_B;

#pragma unroll
        for (int ks = 0; ks < 2; ++ks) {
            uint32_t a_frag[MI][4];
#pragma unroll
            for (int mi = 0; mi < MI; ++mi) {
                uint32_t ad = a_base + (uint32_t)(a_row + mi * 16) * SROW_B
                            + (uint32_t)(ks * 16 + a_col) * 2;
                LDSM_X4(a_frag[mi][0], a_frag[mi][1], a_frag[mi][2], a_frag[mi][3], ad);
            }
#pragma unroll
            for (int s = 0; s < 3; ++s) {
#pragma unroll
                for (int ni = 0; ni < 4; ++ni) {
                    uint32_t bd = w_base + s * W_TILE_B
                                + (uint32_t)(b_row + ni * 8) * SROW_B
                                + (uint32_t)(ks * 16 + b_col) * 2;
                    uint32_t b0, b1;
                    LDSM_X2(b0, b1, bd);
#pragma unroll
                    for (int mi = 0; mi < MI; ++mi)
                        MMA_BF16(acc[mi][ni], a_frag[mi], b0, b1);
                }
            }
        }
        __syncthreads();
    }

    // ---- epilogue part 1: acc + bias -> f32 stage in smem ----
    float* stage = (float*)(smem + SM_STAGE);
    const float* bias_s = (const float*)(smem + SM_BIAS);
#pragma unroll
    for (int mi = 0; mi < MI; ++mi) {
#pragma unroll
        for (int ni = 0; ni < 4; ++ni) {
            int row  = warp_m * (BM / 4) + mi * 16 + (lane >> 2);
            int coll = warp_n * 32 + ni * 8 + (lane & 3) * 2;
            stage[row * STP + coll]           = acc[mi][ni][0] + bias_s[coll];
            stage[row * STP + coll + 1]       = acc[mi][ni][1] + bias_s[coll + 1];
            stage[(row + 8) * STP + coll]     = acc[mi][ni][2] + bias_s[coll];
            stage[(row + 8) * STP + coll + 1] = acc[mi][ni][3] + bias_s[coll + 1];
        }
    }
    __syncthreads();

    // ---- epilogue part 2: LIF scan. BM/32 batches x 128 cols, 1 col/thread ----
    if (tid < (BM / 32) * 128) {
        int n  = tid & 127;
        int lb = tid >> 7;
        float mem = 0.f;
#pragma unroll
        for (int t = 0; t < T_STEPS; ++t) {
            float cc = stage[(lb * 32 + t) * STP + n];
            float r = (mem > 1.0f) ? 1.0f : 0.0f;
            mem = 0.9f * mem + cc - r;
            float s = (mem > 1.0f) ? 1.0f : 0.0f;
            if (FINAL) {
                final_out[(size_t)t * (B_SZ * N) + (size_t)(m0 / 32 + lb) * N + n0 + n] = s;
            } else {
                spk_out[(size_t)(m0 + lb * 32 + t) * N + n0 + n] = __float2bfloat16(s);
            }
        }
    }
}

// ---------------------------------------------------------------------------
// All three weight 3-way bf16 splits in one launch (exact Dekker split)
// ---------------------------------------------------------------------------
__global__ void split_all_kernel(const float* __restrict__ W1,
                                 const float* __restrict__ W2,
                                 const float* __restrict__ W3,
                                 __nv_bfloat16* __restrict__ ws) {
    const size_t WS = (size_t)H1 * H1;
    int i = blockIdx.x * blockDim.x + threadIdx.x;   // 0..131071
    float w; int slot, off;
    if (i < 32768)       { w = W1[i];          slot = 0; off = i; }
    else if (i < 98304)  { w = W2[i - 32768];  slot = 3; off = i - 32768; }
    else                 { w = W3[i - 98304];  slot = 6; off = i - 98304; }
    __nv_bfloat16 h = __float2bfloat16(w);
    float r1 = w - __bfloat162float(h);
    __nv_bfloat16 m = __float2bfloat16(r1);
    float r2 = r1 - __bfloat162float(m);
    __nv_bfloat16 l = __float2bfloat16(r2);
    ws[slot * WS + off]       = h;
    ws[(slot + 1) * WS + off] = m;
    ws[(slot + 2) * WS + off] = l;
}

// ---------------------------------------------------------------------------
// Latency encode + mean over S -> bf16, b-major rows (r = b*32 + t).
// Fast-path binning (provably identical; logf fallback for the rare band).
// ---------------------------------------------------------------------------
__global__ __launch_bounds__(512)
void encode_kernel(const float* __restrict__ x, __nv_bfloat16* __restrict__ out) {
    int b   = blockIdx.x;
    int tid = threadIdx.x;
    int f   = tid & 127;
    int sg  = tid >> 7;

    __shared__ float red[8][F_IN];
    __shared__ int   cnt[T_STEPS * F_IN];

#pragma unroll
    for (int i = 0; i < 8; ++i) cnt[tid + i * 512] = 0;

    const float* xb = x + (size_t)b * S_SZ * F_IN + (size_t)sg * 16 * F_IN + f;

    float vals[16];
    float vmin = FLT_MAX, vmax = -FLT_MAX;
#pragma unroll
    for (int i = 0; i < 16; ++i) {
        float v = xb[i * F_IN];
        v = (v < 0.75f) ? 0.f : v;
        vals[i] = v;
        vmin = fminf(vmin, v);
        vmax = fmaxf(vmax, v);
    }
    red[sg][f]     = vmin;
    red[4 + sg][f] = vmax;
    __syncthreads();

    float gmin = fminf(fminf(red[0][f], red[1][f]), fminf(red[2][f], red[3][f]));
    float gmax = fmaxf(fmaxf(red[4][f], red[5][f]), fmaxf(red[6][f], red[7][f]));
    float denom = gmax - gmin + 1e-8f;

    const float c1   = 0.0100001f;
    const float tmax = 11.512935464920229f;

    int idx_c1;
    {
        float tt = logf(c1 / (c1 - 0.01f)) * 31.0f / tmax;
        float r  = rintf(tt);
        idx_c1 = (int)fminf(fmaxf(r, 0.f), 31.f);
    }

#pragma unroll
    for (int i = 0; i < 16; ++i) {
        float xn = (vals[i] - gmin) / denom;
        float d  = fmaxf(xn, c1);
        int idx;
        if (d == c1)         idx = idx_c1;
        else if (d > 0.07f)  idx = 0;
        else {
            float tt = logf(d / (d - 0.01f)) * 31.0f / tmax;
            float r  = rintf(tt);
            idx = (int)fminf(fmaxf(r, 0.f), 31.f);
        }
        atomicAdd(&cnt[idx * F_IN + f], 1);
    }
    __syncthreads();

#pragma unroll
    for (int i = 0; i < 8; ++i) {
        int flat = tid + i * 512;
        int t = flat >> 7, ff = flat & 127;
        out[((size_t)b * T_STEPS + t) * F_IN + ff] =
            __float2bfloat16((float)cnt[t * F_IN + ff] * 0.015625f);
    }
}

// ---------------------------------------------------------------------------
extern "C" void kernel_launch(void* const* d_in, const int* in_sizes, int n_in,
                              void* d_out, int out_size) {
    const float* x  = (const float*)d_in[0];
    const float* W1 = (const float*)d_in[1];
    const float* b1 = (const float*)d_in[2];
    const float* W2 = (const float*)d_in[3];
    const float* b2 = (const float*)d_in[4];
    const float* W3 = (const float*)d_in[5];
    const float* b3 = (const float*)d_in[6];
    float* out = (float*)d_out;

    __nv_bfloat16 *spk0, *spk1, *spk2, *ws;
    cudaGetSymbolAddress((void**)&spk0, g_spk0);
    cudaGetSymbolAddress((void**)&spk1, g_spk1);
    cudaGetSymbolAddress((void**)&spk2, g_spk2);
    cudaGetSymbolAddress((void**)&ws,   g_wsplit);
    const size_t WS = (size_t)H1 * H1;

    cudaFuncSetAttribute(hmma_gemm_lif_kernel<128, 128, false>, cudaFuncAttributeMaxDynamicSharedMemorySize, SM_TOTAL);
    cudaFuncSetAttribute(hmma_gemm_lif_kernel<256, 128, false>, cudaFuncAttributeMaxDynamicSharedMemorySize, SM_TOTAL);
    cudaFuncSetAttribute(hmma_gemm_lif_kernel<256, 64,  true>,  cudaFuncAttributeMaxDynamicSharedMemorySize, SM_TOTAL);

    split_all_kernel<<<512, 256>>>(W1, W2, W3, ws);
    encode_kernel<<<B_SZ, 512>>>(x, spk0);

    // layer 1: (16384 x 128) @ (256 x 128)^T, fused LIF
    hmma_gemm_lif_kernel<128, 128, false><<<dim3(H1 / 128, M_ROWS / 128), 512, SM_TOTAL>>>(
        spk0, ws + 0 * WS, ws + 1 * WS, ws + 2 * WS, b1, spk1, nullptr, H1);

    // layer 2: (16384 x 256) @ (256 x 256)^T, fused LIF
    hmma_gemm_lif_kernel<256, 128, false><<<dim3(H2 / 128, M_ROWS / 128), 512, SM_TOTAL>>>(
        spk1, ws + 3 * WS, ws + 4 * WS, ws + 5 * WS, b2, spk2, nullptr, H2);

    // layer 3: (16384 x 256) @ (128 x 256)^T, BM=64 tiles -> grid 256, fused LIF
    hmma_gemm_lif_kernel<256, 64, true><<<dim3(H3 / 128, M_ROWS / 64), 512, SM_TOTAL>>>(
        spk2, ws + 6 * WS, ws + 7 * WS, ws + 8 * WS, b3, nullptr, out, H3);
}

// round 8
// speedup vs baseline: 1.0786x; 1.0786x over previous
#include <cuda_runtime.h>
#include <cuda_bf16.h>
#include <math.h>
#include <float.h>
#include <stdint.h>

#define T_STEPS 32
#define B_SZ    512
#define S_SZ    64
#define F_IN    128
#define H1      256
#define H2      256
#define H3      128
#define M_ROWS  (T_STEPS * B_SZ)   // 16384

// ---------------------------------------------------------------------------
// Scratch (__device__ globals). Activation rows: r = b*32 + t (b-major).
// ---------------------------------------------------------------------------
__device__ __nv_bfloat16 g_spk0[M_ROWS * F_IN];
__device__ __nv_bfloat16 g_spk1[M_ROWS * H1];
__device__ __nv_bfloat16 g_spk2[M_ROWS * H2];
__device__ __nv_bfloat16 g_wsplit[9][H1 * H1];   // [layer*3+split][N*K]

// ---------------------------------------------------------------------------
// PTX helpers
// ---------------------------------------------------------------------------
__device__ __forceinline__ uint32_t smem_u32(const void* p) {
    uint32_t a;
    asm("{ .reg .u64 t; cvta.to.shared.u64 t, %1; cvt.u32.u64 %0, t; }" : "=r"(a) : "l"(p));
    return a;
}
#define CP_ASYNC16(dst, src) \
    asm volatile("cp.async.cg.shared.global [%0], [%1], 16;" :: "r"(dst), "l"(src))
#define CP_COMMIT() asm volatile("cp.async.commit_group;")
#define CP_WAIT(N)  asm volatile("cp.async.wait_group %0;" :: "n"(N))

#define LDSM_X4(r0, r1, r2, r3, addr)                                   \
    asm volatile("ldmatrix.sync.aligned.m8n8.x4.shared.b16 "            \
                 "{%0,%1,%2,%3}, [%4];"                                 \
                 : "=r"(r0), "=r"(r1), "=r"(r2), "=r"(r3) : "r"(addr))
#define LDSM_X2(r0, r1, addr)                                           \
    asm volatile("ldmatrix.sync.aligned.m8n8.x2.shared.b16 "            \
                 "{%0,%1}, [%2];" : "=r"(r0), "=r"(r1) : "r"(addr))

#define MMA_BF16(c, a, b0, b1)                                          \
    asm volatile("mma.sync.aligned.m16n8k16.row.col.f32.bf16.bf16.f32 " \
                 "{%0,%1,%2,%3}, {%4,%5,%6,%7}, {%8,%9}, {%0,%1,%2,%3};"\
                 : "+f"((c)[0]), "+f"((c)[1]), "+f"((c)[2]), "+f"((c)[3])\
                 : "r"((a)[0]), "r"((a)[1]), "r"((a)[2]), "r"((a)[3]),  \
                   "r"(b0), "r"(b1))

// ---------------------------------------------------------------------------
// Fused HMMA GEMM + LIF scan. 256 threads / 8 warps (4 m x 2 n).
// CTA tile BM x 64, warp tile (BM/4) x 32, BK=32, double-buffered cp.async.
// Small BN=64 -> 512 CTAs for the big layers -> ~3 CTAs/SM co-resident.
// ---------------------------------------------------------------------------
#define BN        64
#define BK        32
#define SROW_B    80
#define W_TILE_B  (BN * SROW_B)              // 5120 per split
#define SM_BIAS   0                          // 64 floats
#define SM_STAGE  512
#define STP       66                         // epilogue stage pitch (floats)

template<int K, int BM, bool FINAL>
__global__ __launch_bounds__(256, 3)
void hmma_gemm_lif_kernel(const __nv_bfloat16* __restrict__ A,
                          const __nv_bfloat16* __restrict__ Whi,
                          const __nv_bfloat16* __restrict__ Wmid,
                          const __nv_bfloat16* __restrict__ Wlo,
                          const float* __restrict__ bias,
                          __nv_bfloat16* __restrict__ spk_out,
                          float* __restrict__ final_out,
                          int N) {
    constexpr int CHUNKS   = K / BK;
    constexpr int MI       = BM / 64;                  // m16 tiles per warp
    constexpr int A_TILE_B = BM * SROW_B;
    constexpr int STAGE_B  = A_TILE_B + 3 * W_TILE_B;

    extern __shared__ char smem[];
    const uint32_t sb = smem_u32(smem);
    const int tid  = threadIdx.x;
    const int wid  = tid >> 5;
    const int lane = tid & 31;
    const int warp_m = wid & 3;        // 0..3
    const int warp_n = wid >> 2;       // 0..1
    const int m0 = blockIdx.y * BM;
    const int n0 = blockIdx.x * BN;

    if (tid < BN) ((float*)(smem + SM_BIAS))[tid] = bias[n0 + tid];

    const __nv_bfloat16* Wp[3] = {Whi, Wmid, Wlo};

    auto prefetch = [&](int c, int buf) {
        uint32_t st = sb + SM_STAGE + buf * STAGE_B;
        // A tile: BM rows x 32 cols bf16 = BM*4 16B units
#pragma unroll
        for (int u = tid; u < BM * 4; u += 256) {
            int row = u >> 2, col16 = u & 3;
            const char* g = (const char*)(A + (size_t)(m0 + row) * K + c * BK + col16 * 8);
            CP_ASYNC16(st + row * SROW_B + col16 * 16, g);
        }
        // W tiles: 3 x (64 rows x 4 units) = 3 x 256 units
#pragma unroll
        for (int s = 0; s < 3; ++s) {
            uint32_t wst = st + A_TILE_B + s * W_TILE_B;
            int row = tid >> 2, col16 = tid & 3;
            const char* g = (const char*)(Wp[s] + (size_t)(n0 + row) * K + c * BK + col16 * 8);
            CP_ASYNC16(wst + row * SROW_B + col16 * 16, g);
        }
        CP_COMMIT();
    };

    float acc[MI][4][4];
#pragma unroll
    for (int mi = 0; mi < MI; ++mi)
#pragma unroll
        for (int ni = 0; ni < 4; ++ni)
#pragma unroll
            for (int j = 0; j < 4; ++j) acc[mi][ni][j] = 0.f;

    const int a_row = warp_m * (BM / 4) + (lane & 7) + ((lane >> 3) & 1) * 8;
    const int a_col = (lane >> 4) * 8;
    const int lb16  = lane & 15;
    const int b_row = warp_n * 32 + (lb16 & 7);
    const int b_col = ((lb16 >> 3) & 1) * 8;

    prefetch(0, 0);

    for (int c = 0; c < CHUNKS; ++c) {
        int buf = c & 1;
        if (c + 1 < CHUNKS) { prefetch(c + 1, buf ^ 1); CP_WAIT(1); }
        else                { CP_WAIT(0); }
        __syncthreads();

        uint32_t a_base = sb + SM_STAGE + buf * STAGE_B;
        uint32_t w_base = a_base + A_TILE_B;

#pragma unroll
        for (int ks = 0; ks < 2; ++ks) {
            uint32_t a_frag[MI][4];
#pragma unroll
            for (int mi = 0; mi < MI; ++mi) {
                uint32_t ad = a_base + (uint32_t)(a_row + mi * 16) * SROW_B
                            + (uint32_t)(ks * 16 + a_col) * 2;
                LDSM_X4(a_frag[mi][0], a_frag[mi][1], a_frag[mi][2], a_frag[mi][3], ad);
            }
#pragma unroll
            for (int s = 0; s < 3; ++s) {
#pragma unroll
                for (int ni = 0; ni < 4; ++ni) {
                    uint32_t bd = w_base + s * W_TILE_B
                                + (uint32_t)(b_row + ni * 8) * SROW_B
                                + (uint32_t)(ks * 16 + b_col) * 2;
                    uint32_t b0, b1;
                    LDSM_X2(b0, b1, bd);
#pragma unroll
                    for (int mi = 0; mi < MI; ++mi)
                        MMA_BF16(acc[mi][ni], a_frag[mi], b0, b1);
                }
            }
        }
        __syncthreads();
    }

    // ---- epilogue part 1: acc + bias -> f32 stage in smem ----
    float* stage = (float*)(smem + SM_STAGE);
    const float* bias_s = (const float*)(smem + SM_BIAS);
#pragma unroll
    for (int mi = 0; mi < MI; ++mi) {
#pragma unroll
        for (int ni = 0; ni < 4; ++ni) {
            int row  = warp_m * (BM / 4) + mi * 16 + (lane >> 2);
            int coll = warp_n * 32 + ni * 8 + (lane & 3) * 2;
            stage[row * STP + coll]           = acc[mi][ni][0] + bias_s[coll];
            stage[row * STP + coll + 1]       = acc[mi][ni][1] + bias_s[coll + 1];
            stage[(row + 8) * STP + coll]     = acc[mi][ni][2] + bias_s[coll];
            stage[(row + 8) * STP + coll + 1] = acc[mi][ni][3] + bias_s[coll + 1];
        }
    }
    __syncthreads();

    // ---- epilogue part 2: LIF scan. BM/32 batches x 64 cols ----
    if (tid < (BM / 32) * BN) {
        int n  = tid & (BN - 1);
        int lb = tid / BN;
        float mem = 0.f;
#pragma unroll
        for (int t = 0; t < T_STEPS; ++t) {
            float cc = stage[(lb * 32 + t) * STP + n];
            float r = (mem > 1.0f) ? 1.0f : 0.0f;
            mem = 0.9f * mem + cc - r;
            float s = (mem > 1.0f) ? 1.0f : 0.0f;
            if (FINAL) {
                final_out[(size_t)t * (B_SZ * N) + (size_t)(m0 / 32 + lb) * N + n0 + n] = s;
            } else {
                spk_out[(size_t)(m0 + lb * 32 + t) * N + n0 + n] = __float2bfloat16(s);
            }
        }
    }
}

// ---------------------------------------------------------------------------
// All three weight 3-way bf16 splits in one launch (exact Dekker split)
// ---------------------------------------------------------------------------
__global__ void split_all_kernel(const float* __restrict__ W1,
                                 const float* __restrict__ W2,
                                 const float* __restrict__ W3,
                                 __nv_bfloat16* __restrict__ ws) {
    const size_t WS = (size_t)H1 * H1;
    int i = blockIdx.x * blockDim.x + threadIdx.x;   // 0..131071
    float w; int slot, off;
    if (i < 32768)       { w = W1[i];          slot = 0; off = i; }
    else if (i < 98304)  { w = W2[i - 32768];  slot = 3; off = i - 32768; }
    else                 { w = W3[i - 98304];  slot = 6; off = i - 98304; }
    __nv_bfloat16 h = __float2bfloat16(w);
    float r1 = w - __bfloat162float(h);
    __nv_bfloat16 m = __float2bfloat16(r1);
    float r2 = r1 - __bfloat162float(m);
    __nv_bfloat16 l = __float2bfloat16(r2);
    ws[slot * WS + off]       = h;
    ws[(slot + 1) * WS + off] = m;
    ws[(slot + 2) * WS + off] = l;
}

// ---------------------------------------------------------------------------
// Latency encode + mean over S -> bf16, b-major rows (r = b*32 + t).
// Fast-path binning (provably identical; logf fallback for the rare band).
// ---------------------------------------------------------------------------
__global__ __launch_bounds__(512)
void encode_kernel(const float* __restrict__ x, __nv_bfloat16* __restrict__ out) {
    int b   = blockIdx.x;
    int tid = threadIdx.x;
    int f   = tid & 127;
    int sg  = tid >> 7;

    __shared__ float red[8][F_IN];
    __shared__ int   cnt[T_STEPS * F_IN];

#pragma unroll
    for (int i = 0; i < 8; ++i) cnt[tid + i * 512] = 0;

    const float* xb = x + (size_t)b * S_SZ * F_IN + (size_t)sg * 16 * F_IN + f;

    float vals[16];
    float vmin = FLT_MAX, vmax = -FLT_MAX;
#pragma unroll
    for (int i = 0; i < 16; ++i) {
        float v = xb[i * F_IN];
        v = (v < 0.75f) ? 0.f : v;
        vals[i] = v;
        vmin = fminf(vmin, v);
        vmax = fmaxf(vmax, v);
    }
    red[sg][f]     = vmin;
    red[4 + sg][f] = vmax;
    __syncthreads();

    float gmin = fminf(fminf(red[0][f], red[1][f]), fminf(red[2][f], red[3][f]));
    float gmax = fmaxf(fmaxf(red[4][f], red[5][f]), fmaxf(red[6][f], red[7][f]));
    float denom = gmax - gmin + 1e-8f;

    const float c1   = 0.0100001f;
    const float tmax = 11.512935464920229f;

    int idx_c1;
    {
        float tt = logf(c1 / (c1 - 0.01f)) * 31.0f / tmax;
        float r  = rintf(tt);
        idx_c1 = (int)fminf(fmaxf(r, 0.f), 31.f);
    }

#pragma unroll
    for (int i = 0; i < 16; ++i) {
        float xn = (vals[i] - gmin) / denom;
        float d  = fmaxf(xn, c1);
        int idx;
        if (d == c1)         idx = idx_c1;
        else if (d > 0.07f)  idx = 0;
        else {
            float tt = logf(d / (d - 0.01f)) * 31.0f / tmax;
            float r  = rintf(tt);
            idx = (int)fminf(fmaxf(r, 0.f), 31.f);
        }
        atomicAdd(&cnt[idx * F_IN + f], 1);
    }
    __syncthreads();

#pragma unroll
    for (int i = 0; i < 8; ++i) {
        int flat = tid + i * 512;
        int t = flat >> 7, ff = flat & 127;
        out[((size_t)b * T_STEPS + t) * F_IN + ff] =
            __float2bfloat16((float)cnt[t * F_IN + ff] * 0.015625f);
    }
}

// ---------------------------------------------------------------------------
extern "C" void kernel_launch(void* const* d_in, const int* in_sizes, int n_in,
                              void* d_out, int out_size) {
    const float* x  = (const float*)d_in[0];
    const float* W1 = (const float*)d_in[1];
    const float* b1 = (const float*)d_in[2];
    const float* W2 = (const float*)d_in[3];
    const float* b2 = (const float*)d_in[4];
    const float* W3 = (const float*)d_in[5];
    const float* b3 = (const float*)d_in[6];
    float* out = (float*)d_out;

    __nv_bfloat16 *spk0, *spk1, *spk2, *ws;
    cudaGetSymbolAddress((void**)&spk0, g_spk0);
    cudaGetSymbolAddress((void**)&spk1, g_spk1);
    cudaGetSymbolAddress((void**)&spk2, g_spk2);
    cudaGetSymbolAddress((void**)&ws,   g_wsplit);
    const size_t WS = (size_t)H1 * H1;

    constexpr int SMT128 = SM_STAGE + 2 * (128 * SROW_B + 3 * W_TILE_B);  // 51712
    cudaFuncSetAttribute(hmma_gemm_lif_kernel<128, 128, false>, cudaFuncAttributeMaxDynamicSharedMemorySize, SMT128);
    cudaFuncSetAttribute(hmma_gemm_lif_kernel<256, 128, false>, cudaFuncAttributeMaxDynamicSharedMemorySize, SMT128);
    cudaFuncSetAttribute(hmma_gemm_lif_kernel<256, 128, true>,  cudaFuncAttributeMaxDynamicSharedMemorySize, SMT128);

    split_all_kernel<<<512, 256>>>(W1, W2, W3, ws);
    encode_kernel<<<B_SZ, 512>>>(x, spk0);

    // layer 1: (16384 x 128) @ (256 x 128)^T, grid (4, 128) = 512 CTAs
    hmma_gemm_lif_kernel<128, 128, false><<<dim3(H1 / BN, M_ROWS / 128), 256, SMT128>>>(
        spk0, ws + 0 * WS, ws + 1 * WS, ws + 2 * WS, b1, spk1, nullptr, H1);

    // layer 2: (16384 x 256) @ (256 x 256)^T, grid (4, 128) = 512 CTAs
    hmma_gemm_lif_kernel<256, 128, false><<<dim3(H2 / BN, M_ROWS / 128), 256, SMT128>>>(
        spk1, ws + 3 * WS, ws + 4 * WS, ws + 5 * WS, b2, spk2, nullptr, H2);

    // layer 3: (16384 x 256) @ (128 x 256)^T, grid (2, 128) = 256 CTAs
    hmma_gemm_lif_kernel<256, 128, true><<<dim3(H3 / BN, M_ROWS / 128), 256, SMT128>>>(
        spk2, ws + 6 * WS, ws + 7 * WS, ws + 8 * WS, b3, nullptr, out, H3);
}